// round 3
// baseline (speedup 1.0000x reference)
#include <cuda_runtime.h>

// PartialSum: out[b, p] = sum over 64 contiguous floats of x[b, p*64 : (p+1)*64]
// x: [2048, 65536] f32  -> out: [2048, 1024] f32 (2,097,152 partitions)
//
// 2 threads per partition, 8 independent LDG.128 per thread (32 floats each),
// one shfl_xor to combine halves, even lane writes. MLP_p1=8 to keep the
// L1tex queue full and hide DRAM latency (R1 at MLP=1 stalled at 65% DRAM).

__global__ void __launch_bounds__(256) partial_sum_kernel(
    const float4* __restrict__ x4, float* __restrict__ out)
{
    int tid = blockIdx.x * 256 + threadIdx.x;     // half-partition index
    // float4 base: partition (tid>>1) starts at (tid>>1)*16 float4s;
    // half (tid&1) adds 8 float4s. == tid*8.
    const float4* p = x4 + ((long long)tid << 3);

    float4 v0 = __ldg(&p[0]);
    float4 v1 = __ldg(&p[1]);
    float4 v2 = __ldg(&p[2]);
    float4 v3 = __ldg(&p[3]);
    float4 v4 = __ldg(&p[4]);
    float4 v5 = __ldg(&p[5]);
    float4 v6 = __ldg(&p[6]);
    float4 v7 = __ldg(&p[7]);

    float s0 = (v0.x + v0.y) + (v0.z + v0.w);
    float s1 = (v1.x + v1.y) + (v1.z + v1.w);
    float s2 = (v2.x + v2.y) + (v2.z + v2.w);
    float s3 = (v3.x + v3.y) + (v3.z + v3.w);
    float s4 = (v4.x + v4.y) + (v4.z + v4.w);
    float s5 = (v5.x + v5.y) + (v5.z + v5.w);
    float s6 = (v6.x + v6.y) + (v6.z + v6.w);
    float s7 = (v7.x + v7.y) + (v7.z + v7.w);

    float s = ((s0 + s1) + (s2 + s3)) + ((s4 + s5) + (s6 + s7));

    // Combine the two halves of the partition (lanes 2k and 2k+1).
    s += __shfl_xor_sync(0xffffffffu, s, 1);

    if ((tid & 1) == 0)
        out[tid >> 1] = s;
}

extern "C" void kernel_launch(void* const* d_in, const int* in_sizes, int n_in,
                              void* d_out, int out_size)
{
    const float4* x4 = (const float4*)d_in[0];
    float* out = (float*)d_out;

    int n_half = out_size * 2;                      // 4,194,304 threads
    int threads = 256;
    int blocks = (n_half + threads - 1) / threads;  // 16384

    partial_sum_kernel<<<blocks, threads>>>(x4, out);
}

// round 4
// speedup vs baseline: 1.4582x; 1.4582x over previous
#include <cuda_runtime.h>

// PartialSum: out[b, p] = sum over 64 contiguous floats of x[b, p*64 : (p+1)*64]
// x: [2048, 65536] f32  -> out: [2048, 1024] f32 (2,097,152 partitions)
//
// Coalesced + MLP=4: each thread issues 4 independent LDG.128, each of which
// is fully warp-coalesced (contiguous 512B per warp). 16 lanes per partition,
// 4 independent shfl_down reduction trees (ILP), writer lane stores 4 outputs.
// Block covers 1024 float4 = 4096 floats = 64 partitions.

__global__ void __launch_bounds__(256) partial_sum_kernel(
    const float4* __restrict__ x4, float* __restrict__ out)
{
    int t = threadIdx.x;
    int base = blockIdx.x * 1024 + t;              // float4 index of load 0

    // 4 independent, individually-coalesced loads (front-batched -> MLP=4)
    float4 a = __ldg(&x4[base]);
    float4 b = __ldg(&x4[base + 256]);
    float4 c = __ldg(&x4[base + 512]);
    float4 d = __ldg(&x4[base + 768]);

    float sa = (a.x + a.y) + (a.z + a.w);
    float sb = (b.x + b.y) + (b.z + b.w);
    float sc = (c.x + c.y) + (c.z + c.w);
    float sd = (d.x + d.y) + (d.z + d.w);

    // 4 independent 16-lane reduction trees (interleaved for ILP).
    #pragma unroll
    for (int off = 8; off > 0; off >>= 1) {
        sa += __shfl_down_sync(0xffffffffu, sa, off, 16);
        sb += __shfl_down_sync(0xffffffffu, sb, off, 16);
        sc += __shfl_down_sync(0xffffffffu, sc, off, 16);
        sd += __shfl_down_sync(0xffffffffu, sd, off, 16);
    }

    if ((t & 15) == 0) {
        int p = blockIdx.x * 64 + (t >> 4);        // partition of load 0
        out[p]      = sa;
        out[p + 16] = sb;
        out[p + 32] = sc;
        out[p + 48] = sd;
    }
}

extern "C" void kernel_launch(void* const* d_in, const int* in_sizes, int n_in,
                              void* d_out, int out_size)
{
    const float4* x4 = (const float4*)d_in[0];
    float* out = (float*)d_out;

    int blocks = out_size / 64;                    // 2,097,152 / 64 = 32768
    partial_sum_kernel<<<blocks, 256>>>(x4, out);
}